// round 4
// baseline (speedup 1.0000x reference)
#include <cuda_runtime.h>

// Fixed problem dims
#define NB 4
#define NQv 512
#define MMv 512
#define DDv 256
#define HHv 256

// Scratch (device globals: no allocations allowed)
__device__ float g_q[NB * NQv * HHv];    // projected q, [b*NQ+n][h]
__device__ float g_kT[NB * HHv * MMv];   // projected k, transposed: [b][h][m]
__device__ float g_sc[NB * NQv * MMv];   // raw scores [b][n][m]

// Pipeline counters (zero-initialized; self-reset by last block each run)
//  [0,32):   q-proj row-tile counters (b*8 + rowtile), target 4
//  [32,40):  kT m-half counters (32 + b*2 + mh), target 16
//  [64,320): score-done counters (64 + b*64 + qc), target 2
//  [384]:    softav done ticket
__device__ int g_cnt[512];

#define CNT_DONE 384

__device__ __forceinline__ float ftanh(float x) {
    float y; asm("tanh.approx.f32 %0, %1;" : "=f"(y) : "f"(x)); return y;
}
__device__ __forceinline__ float fex2(float x) {
    float y; asm("ex2.approx.f32 %0, %1;" : "=f"(y) : "f"(x)); return y;
}
__device__ __forceinline__ unsigned long long pk2(float a, float b) {
    unsigned long long r; asm("mov.b64 %0, {%1, %2};" : "=l"(r) : "f"(a), "f"(b)); return r;
}
__device__ __forceinline__ void fma2(unsigned long long &d, unsigned long long a, unsigned long long b) {
    asm("fma.rn.f32x2 %0, %1, %2, %0;" : "+l"(d) : "l"(a), "l"(b));
}
__device__ __forceinline__ float2 up2(unsigned long long v) {
    float2 r; asm("mov.b64 {%0, %1}, %2;" : "=f"(r.x), "=f"(r.y) : "l"(v)); return r;
}

__device__ __forceinline__ void spin_cnt(int idx, int tgt) {
    while (atomicAdd(&g_cnt[idx], 0) < tgt) __nanosleep(100);
}

// Shared memory: one block uses exactly one branch.
//  proj:   As 16x68 f32 (4352B) + Bs 16x64 f32 (4096B)          = 8448
//  score:  qs 8x264 f32 (8448B) + ws 256 f32 (1024B)            = 9472
//  softav: sc 8x512 f32 (16384B, ps[2][8][128] f2 overlaid) + 32 = 16416
__shared__ __align__(16) unsigned char SM[16512];

__global__ __launch_bounds__(256) void fused_kernel(const float* __restrict__ query,
                                                    const float* __restrict__ key,
                                                    const float* __restrict__ value,
                                                    const float* __restrict__ Wq,
                                                    const float* __restrict__ Wk,
                                                    const float* __restrict__ Wv,
                                                    float* __restrict__ out)
{
    int t = threadIdx.x;
    int bid = blockIdx.x;

    if (bid < 256) {
        // ================= PROJECTION (64x64 tile, 4x4 micro) =================
        float (*As)[68] = (float(*)[68])SM;
        float (*Bs)[64] = (float(*)[64])(SM + 4352);

        int is_k = bid >> 7;
        int local = bid & 127;
        int row0 = (local >> 2) * 64;
        int col0 = (local & 3) * 64;
        const float* A = is_k ? key : query;
        const float* B = is_k ? Wk : Wq;

        int tx = t & 15, ty = t >> 4;
        int arow = t >> 2, akq = t & 3;
        int bk = t >> 4, bh = t & 15;

        unsigned long long acc[4][2];
#pragma unroll
        for (int i = 0; i < 4; i++) { acc[i][0] = 0ull; acc[i][1] = 0ull; }

        for (int k0 = 0; k0 < DDv; k0 += 16) {
            float4 a4 = *(const float4*)(A + (row0 + arow) * DDv + k0 + akq * 4);
            float4 b4 = *(const float4*)(B + (k0 + bk) * HHv + col0 + bh * 4);
            As[akq * 4 + 0][arow] = a4.x;
            As[akq * 4 + 1][arow] = a4.y;
            As[akq * 4 + 2][arow] = a4.z;
            As[akq * 4 + 3][arow] = a4.w;
            *(float4*)&Bs[bk][bh * 4] = b4;
            __syncthreads();
#pragma unroll
            for (int k = 0; k < 16; k++) {
                const unsigned long long* br = (const unsigned long long*)&Bs[k][tx * 4];
                unsigned long long b0 = br[0], b1 = br[1];
#pragma unroll
                for (int i = 0; i < 4; i++) {
                    float a = As[k][ty * 4 + i];
                    unsigned long long aa = pk2(a, a);
                    fma2(acc[i][0], aa, b0);
                    fma2(acc[i][1], aa, b1);
                }
            }
            __syncthreads();
        }

#pragma unroll
        for (int i = 0; i < 4; i++) {
            int row = row0 + ty * 4 + i;
            int col = col0 + tx * 4;
            float2 c0 = up2(acc[i][0]);
            float2 c1 = up2(acc[i][1]);
            if (!is_k) {
                *(float4*)(g_q + row * HHv + col) = make_float4(c0.x, c0.y, c1.x, c1.y);
            } else {
                int bb = row >> 9, m = row & 511;
                float* base = g_kT + (bb * HHv) * MMv + m;
                base[(col + 0) * MMv] = c0.x;
                base[(col + 1) * MMv] = c0.y;
                base[(col + 2) * MMv] = c1.x;
                base[(col + 3) * MMv] = c1.y;
            }
        }

        __threadfence();
        __syncthreads();
        if (t == 0) {
            int idx = is_k ? (32 + (row0 >> 9) * 2 + ((row0 >> 8) & 1))
                           : (row0 >> 6);
            atomicAdd(&g_cnt[idx], 1);
        }

    } else if (bid < 768) {
        // ================= SCORES (8q x 256m per block) =================
        float (*qs)[264] = (float(*)[264])SM;
        float* ws = (float*)(SM + 8448);

        int s = bid - 256;
        int mc = s & 1;
        int qc = (s >> 1) & 63;
        int b = s >> 7;
        int n0 = qc * 8;
        int m = mc * 256 + t;

        // Wait for q row-tile (4 col blocks) + kT m-half (16 blocks)
        if (t == 0) {
            spin_cnt(b * 8 + (n0 >> 6), 4);
            spin_cnt(32 + b * 2 + mc, 16);
            __threadfence();
        }
        __syncthreads();

        // Stage 8 projected-q rows + W_v
#pragma unroll
        for (int r = 0; r < 2; r++) {
            int idx = t + r * 256;
            int q = idx >> 6, c4 = idx & 63;
            float4 v = ((const float4*)(g_q + (b * NQv + n0 + q) * HHv))[c4];
            *(float4*)&qs[q][c4 * 4] = v;
        }
        if (t < 64) ((float4*)ws)[t] = ((const float4*)Wv)[t];
        __syncthreads();

        float acc[8];
#pragma unroll
        for (int q = 0; q < 8; q++) acc[q] = 0.f;

        const float* kb = g_kT + (b * HHv) * MMv + m;
#pragma unroll 4
        for (int h = 0; h < HHv; h++) {
            float kv = kb[h * MMv];
            float wv = ws[h];
#pragma unroll
            for (int q = 0; q < 8; q++)
                acc[q] = fmaf(wv, ftanh(qs[q][h] + kv), acc[q]);
        }

#pragma unroll
        for (int q = 0; q < 8; q++)
            g_sc[(b * NQv + n0 + q) * MMv + m] = acc[q];

        __threadfence();
        __syncthreads();
        if (t == 0) atomicAdd(&g_cnt[64 + b * 64 + qc], 1);

    } else {
        // ================= SOFTMAX + AV (8q per block) =================
        float (*sc)[512] = (float(*)[512])SM;
        float2* psB = (float2*)SM;           // overlaid on sc after AV accumulation
        float* inv_s = (float*)(SM + 16384);

        int v = bid - 768;
        int b = v >> 6;
        int qc = v & 63;
        int n0 = qc * 8;
        int w = t >> 5, lane = t & 31;

        if (t == 0) { spin_cnt(64 + b * 64 + qc, 2); __threadfence(); }
        __syncthreads();

        // Softmax: warp w handles query row w
        {
            const float* srow = g_sc + (b * NQv + n0 + w) * MMv;
            float vals[16];
            float vmax = -1e30f;
#pragma unroll
            for (int j = 0; j < 16; j++) {
                vals[j] = srow[lane + j * 32];
                vmax = fmaxf(vmax, vals[j]);
            }
#pragma unroll
            for (int o = 16; o > 0; o >>= 1)
                vmax = fmaxf(vmax, __shfl_xor_sync(0xffffffffu, vmax, o));
            float sum = 0.f;
#pragma unroll
            for (int j = 0; j < 16; j++) {
                float p = fex2((vals[j] - vmax) * 1.4426950408889634f);
                sc[w][lane + j * 32] = p;
                sum += p;
            }
#pragma unroll
            for (int o = 16; o > 0; o >>= 1)
                sum += __shfl_xor_sync(0xffffffffu, sum, o);
            if (lane == 0) inv_s[w] = 1.0f / sum;
        }
        __syncthreads();

        // AV
        int mg = t >> 7;
        int vg = t & 127;
        const float* vbase = value + (b * MMv + mg * 256) * DDv + vg * 2;
        unsigned long long acc[8];
#pragma unroll
        for (int q = 0; q < 8; q++) acc[q] = 0ull;
#pragma unroll 4
        for (int mm = 0; mm < 256; mm++) {
            float2 vv = *(const float2*)(vbase + mm * DDv);
            unsigned long long v2 = pk2(vv.x, vv.y);
            int m = mg * 256 + mm;
#pragma unroll
            for (int q = 0; q < 8; q++) {
                float a = sc[q][m];
                fma2(acc[q], pk2(a, a), v2);
            }
        }
        __syncthreads();   // everyone done reading sc; overlay ps on it
#pragma unroll
        for (int q = 0; q < 8; q++) psB[(mg * 8 + q) * 128 + vg] = up2(acc[q]);
        __syncthreads();

        // Reduce 2 m-partials, scale, write out (1024 f2 over 256 thr = 4 it)
#pragma unroll
        for (int r = 0; r < 4; r++) {
            int p = t + r * 256;
            int q = p >> 7, v2i = p & 127;
            float2 s0 = psB[(0 * 8 + q) * 128 + v2i];
            float2 s1 = psB[(1 * 8 + q) * 128 + v2i];
            float iv = inv_s[q];
            ((float2*)out)[(b * NQv + n0 + q) * 128 + v2i] =
                make_float2((s0.x + s1.x) * iv, (s0.y + s1.y) * iv);
        }

        // Last-block counter reset (safe: ticket==255 implies all waits passed)
        __syncthreads();
        if (t == 0) {
            int ticket = atomicAdd(&g_cnt[CNT_DONE], 1);
            if (ticket == 255) {
                for (int i = 0; i <= CNT_DONE; i++) atomicExch(&g_cnt[i], 0);
            }
        }
    }
}

extern "C" void kernel_launch(void* const* d_in, const int* in_sizes, int n_in,
                              void* d_out, int out_size)
{
    const float* query = (const float*)d_in[0];
    const float* key   = (const float*)d_in[1];
    const float* value = (const float*)d_in[2];
    const float* Wq    = (const float*)d_in[3];
    const float* Wk    = (const float*)d_in[4];
    const float* Wv    = (const float*)d_in[5];
    float* out = (float*)d_out;

    fused_kernel<<<1024, 256>>>(query, key, value, Wq, Wk, Wv, out);
}